// round 5
// baseline (speedup 1.0000x reference)
#include <cuda_runtime.h>
#include <cstdint>

#define N_NODES 13
#define N_REAL  12
#define BB      4
#define CC      3
#define HH      256
#define WW      256
#define EE      37
#define HWSZ    (HH*WW)

// Packed activation row: 132 float2. idx 0 = pair {0, a[127]} (j=-1),
// idx 1+j = {a[j], a[j+128]} (j=0..127), idx 129 = {a[128],0}, idx 130 = {a[129],0},
// idx 131 = {0,0} pad. Row = 1056 B (16B-aligned).
#define PROW 132
#define NROWS_TOTAL (N_NODES*BB*CC*HH)       // 39936 packed rows
#define TROWS 11
#define TILE_F2 (CC*TROWS*PROW)              // 4356 float2
#define TILE_BYTES (TILE_F2*8)               // 34848 B
typedef unsigned long long ull;

__device__ float2 g_pk[NROWS_TOTAL*PROW];    // ~42 MB packed sigmoid activations

__device__ __forceinline__ void upk2(ull v, float& lo, float& hi){
  asm("mov.b64 {%0, %1}, %2;" : "=f"(lo), "=f"(hi) : "l"(v));
}
__device__ __forceinline__ ull ffma2(ull a, ull b, ull c){
  ull d; asm("fma.rn.f32x2 %0, %1, %2, %3;" : "=l"(d) : "l"(a), "l"(b), "l"(c));
  return d;
}
__device__ __forceinline__ void cp16(uint32_t s, const void* g){
  asm volatile("cp.async.cg.shared.global [%0], [%1], 16;" :: "r"(s), "l"(g));
}
__device__ __forceinline__ float sigf(float x){
  return __fdividef(1.f, 1.f + __expf(-x));
}

// ---------- pass 1: sigmoid + pack ----------
__global__ void sigmoid_pack_kernel(const float* __restrict__ x, int npairs){
  int idx = blockIdx.x*blockDim.x + threadIdx.x;
  if (idx >= npairs) return;
  int rid = idx / PROW;
  int jj  = idx - rid*PROW;
  const float* in = x + (size_t)rid*WW;
  float lo, hi;
  if (jj == 0)        { lo = 0.f;              hi = sigf(__ldg(in+127)); }
  else if (jj <= 128) { int j = jj-1; lo = sigf(__ldg(in+j)); hi = sigf(__ldg(in+j+128)); }
  else if (jj == 129) { lo = sigf(__ldg(in+128)); hi = 0.f; }
  else if (jj == 130) { lo = sigf(__ldg(in+129)); hi = 0.f; }
  else                { lo = 0.f; hi = 0.f; }
  g_pk[(size_t)rid*PROW + jj] = make_float2(lo, hi);
}

// ---------- pass 2: conv + segment mean; cp.async double-buffered packed tiles ----
// Block (32,4): thread (tx,ty): out rows 2ty,2ty+1 of an 8-row stripe; pair cols
// q = tx+32m (m=0..3) covering out columns {q, q+128}.
extern __shared__ float2 dynsmem[];

__global__ void __launch_bounds__(128, 2) conv_kernel(
    const float* __restrict__ Wt,   // [E,3,3,4,4]
    const float* __restrict__ Bs,   // [E,3]
    const int*   __restrict__ esrc,
    const int*   __restrict__ edst,
    float*       __restrict__ out)  // [12,4,3,256,256]
{
  __shared__ __align__(16) float2 w_all[4*144];  // {w,w} pairs for up to 4 edges
  __shared__ int s_eidx[4], s_src[4], s_deg;

  const int v   = blockIdx.z;
  const int b   = blockIdx.y;
  const int y0  = blockIdx.x * 8;
  const int tx  = threadIdx.x;
  const int ty  = threadIdx.y;
  const int tid = ty*32 + tx;
  const int r0  = 2*ty;

  float2* buf[2] = { dynsmem, dynsmem + TILE_F2 };
  const uint32_t dyn_u32 = (uint32_t)__cvta_generic_to_shared(dynsmem);

  // Zero out-of-range tile rows once (stay zero across edges; fill skips them).
  {
    const float2 z2 = make_float2(0.f,0.f);
    for (int bi=0; bi<2; bi++){
      float2* T = buf[bi];
      #pragma unroll
      for (int rr=0; rr<TROWS; rr++){
        int gy = y0 + rr - 1;
        if ((unsigned)gy >= (unsigned)HH){
          for (int ci=0; ci<CC; ci++)
            for (int i=tid; i<PROW; i+=128)
              T[(ci*TROWS+rr)*PROW + i] = z2;
        }
      }
    }
  }

  // Edge scan + weight/bias preload.
  if (tid == 0){
    int d = 0;
    for (int e=0; e<EE; e++)
      if (__ldg(&edst[e]) == v){ s_eidx[d]=e; s_src[d]=__ldg(&esrc[e]); d++; }
    s_deg = d;
  }
  __syncthreads();
  const int deg = s_deg;
  for (int i=0; i<deg; i++)
    for (int j=tid; j<144; j+=128){
      float w = __ldg(&Wt[s_eidx[i]*144 + j]);
      w_all[i*144 + j] = make_float2(w, w);
    }
  float bsum[3] = {0.f,0.f,0.f};
  for (int i=0; i<deg; i++)
    #pragma unroll
    for (int co=0; co<3; co++) bsum[co] += __ldg(&Bs[s_eidx[i]*3+co]);

  ull acc[3][2][4];
  #pragma unroll
  for (int co=0; co<3; co++)
    #pragma unroll
    for (int rl=0; rl<2; rl++)
      #pragma unroll
      for (int m=0; m<4; m++) acc[co][rl][m] = 0ull;

  // Async fill: pure contiguous copy of packed rows (33 rows x 66 x 16B).
  auto fill_async = [&](int bi, int src_node){
    const size_t nb = ((size_t)src_node*BB + b)*CC;
    uint32_t t_u32 = dyn_u32 + (uint32_t)(bi*TILE_BYTES);
    for (int i = tid; i < CC*TROWS*66; i += 128){
      int t = i / 66;                   // tile row 0..32
      int c = i - t*66;                 // 16B chunk
      int ci = t / TROWS;
      int rr = t - ci*TROWS;
      int gy = y0 + rr - 1;
      if ((unsigned)gy < (unsigned)HH){
        const char* gp = (const char*)(g_pk + ((nb + ci)*HH + gy)*(size_t)PROW) + c*16;
        cp16(t_u32 + (uint32_t)(t*(PROW*8) + c*16), gp);
      }
    }
  };

  __syncthreads();
  fill_async(0, s_src[0]);
  asm volatile("cp.async.commit_group;" ::: "memory");
  asm volatile("cp.async.wait_group 0;" ::: "memory");
  __syncthreads();

  for (int i=0; i<deg; i++){
    const float2* cur = buf[i & 1];
    if (i+1 < deg) fill_async((i+1) & 1, s_src[i+1]);
    asm volatile("cp.async.commit_group;" ::: "memory");

    const float2* wbase = w_all + i*144;
    #pragma unroll
    for (int ci=0; ci<3; ci++){
      const ull* rb = (const ull*)(cur + ci*(TROWS*PROW)) + tx;
      ull A[4][4], B[4][4];
      {
        const ull* rp = rb + (size_t)r0*PROW;
        #pragma unroll
        for (int m=0; m<4; m++)
          #pragma unroll
          for (int k=0; k<4; k++) A[m][k] = rp[32*m + k];
      }
      #pragma unroll
      for (int ky=0; ky<4; ky++){
        const ull* rp = rb + (size_t)(r0+ky+1)*PROW;
        #pragma unroll
        for (int m=0; m<4; m++)
          #pragma unroll
          for (int k=0; k<4; k++) B[m][k] = rp[32*m + k];

        #pragma unroll
        for (int co=0; co<3; co++){
          const ulonglong2* wp =
              (const ulonglong2*)(wbase + (co*3+ci)*16 + ky*4);
          ulonglong2 w01 = wp[0], w23 = wp[1];   // 2x LDS.128 broadcast
          #pragma unroll
          for (int m=0; m<4; m++){
            acc[co][0][m] = ffma2(A[m][0], w01.x, acc[co][0][m]);
            acc[co][0][m] = ffma2(A[m][1], w01.y, acc[co][0][m]);
            acc[co][0][m] = ffma2(A[m][2], w23.x, acc[co][0][m]);
            acc[co][0][m] = ffma2(A[m][3], w23.y, acc[co][0][m]);
            acc[co][1][m] = ffma2(B[m][0], w01.x, acc[co][1][m]);
            acc[co][1][m] = ffma2(B[m][1], w01.y, acc[co][1][m]);
            acc[co][1][m] = ffma2(B[m][2], w23.x, acc[co][1][m]);
            acc[co][1][m] = ffma2(B[m][3], w23.y, acc[co][1][m]);
          }
        }
        if (ky < 3){
          #pragma unroll
          for (int m=0; m<4; m++)
            #pragma unroll
            for (int k=0; k<4; k++) A[m][k] = B[m][k];   // renamed by full unroll
        }
      }
    }

    asm volatile("cp.async.wait_group 0;" ::: "memory");
    __syncthreads();
  }

  // Epilogue: bias + mean, store both columns of each pair.
  const float inv = 1.f / (float)deg;
  #pragma unroll
  for (int co=0; co<3; co++){
    #pragma unroll
    for (int rl=0; rl<2; rl++){
      float* ob = out + (((size_t)v*BB + b)*CC + co)*HWSZ + (y0 + r0 + rl)*WW;
      #pragma unroll
      for (int m=0; m<4; m++){
        float lo, hi;
        upk2(acc[co][rl][m], lo, hi);
        int x = tx + 32*m;
        ob[x]       = (lo + bsum[co]) * inv;
        ob[x + 128] = (hi + bsum[co]) * inv;
      }
    }
  }
}

extern "C" void kernel_launch(void* const* d_in, const int* in_sizes, int n_in,
                              void* d_out, int out_size){
  const float* states  = (const float*)d_in[0];
  const float* weights = (const float*)d_in[1];
  const float* bias    = (const float*)d_in[2];
  const int*   esrc    = (const int*)d_in[3];
  const int*   edst    = (const int*)d_in[4];
  float*       out     = (float*)d_out;

  const int npairs = NROWS_TOTAL * PROW;              // 5,271,552
  sigmoid_pack_kernel<<<(npairs + 255)/256, 256>>>(states, npairs);

  static int smem_set = 0;
  if (!smem_set){
    cudaFuncSetAttribute(conv_kernel, cudaFuncAttributeMaxDynamicSharedMemorySize,
                         2*TILE_BYTES);
    smem_set = 1;
  }
  dim3 grid(HH/8, BB, N_REAL);
  dim3 block(32, 4);
  conv_kernel<<<grid, block, 2*TILE_BYTES>>>(weights, bias, esrc, edst, out);
}

// round 6
// speedup vs baseline: 1.1682x; 1.1682x over previous
#include <cuda_runtime.h>
#include <cstdint>

#define N_NODES 13
#define N_REAL  12
#define BB      4
#define CC      3
#define HH      256
#define WW      256
#define EE      37
#define HWSZ    (HH*WW)

// Packed activation row: 132 float2. idx 0 = {0, a[127]}, idx 1+j = {a[j], a[j+128]}
// (j=0..127), idx 129 = {a[128],0}, idx 130 = {a[129],0}, idx 131 = pad.
#define PROW 132
#define NROWS_TOTAL (N_NODES*BB*CC*HH)
#define TROWS 11
#define PLANE_F2 (TROWS*PROW)          // 1452 float2 per ci-plane tile
#define PLANE_BYTES (PLANE_F2*8)       // 11616 B
typedef unsigned long long ull;

__device__ float2 g_pk[NROWS_TOTAL*PROW];   // ~42 MB packed sigmoid activations

__device__ __forceinline__ void upk2(ull v, float& lo, float& hi){
  asm("mov.b64 {%0, %1}, %2;" : "=f"(lo), "=f"(hi) : "l"(v));
}
__device__ __forceinline__ ull ffma2(ull a, ull b, ull c){
  ull d; asm("fma.rn.f32x2 %0, %1, %2, %3;" : "=l"(d) : "l"(a), "l"(b), "l"(c));
  return d;
}
__device__ __forceinline__ void cp16(uint32_t s, const void* g){
  asm volatile("cp.async.cg.shared.global [%0], [%1], 16;" :: "r"(s), "l"(g));
}
__device__ __forceinline__ float sigf(float x){
  return __fdividef(1.f, 1.f + __expf(-x));
}

// ---------- pass 1: sigmoid + pack ----------
__global__ void sigmoid_pack_kernel(const float* __restrict__ x, int npairs){
  int idx = blockIdx.x*blockDim.x + threadIdx.x;
  if (idx >= npairs) return;
  int rid = idx / PROW;
  int jj  = idx - rid*PROW;
  const float* in = x + (size_t)rid*WW;
  float lo, hi;
  if (jj == 0)        { lo = 0.f;                hi = sigf(__ldg(in+127)); }
  else if (jj <= 128) { int j = jj-1; lo = sigf(__ldg(in+j)); hi = sigf(__ldg(in+j+128)); }
  else if (jj == 129) { lo = sigf(__ldg(in+128)); hi = 0.f; }
  else if (jj == 130) { lo = sigf(__ldg(in+129)); hi = 0.f; }
  else                { lo = 0.f; hi = 0.f; }
  g_pk[(size_t)rid*PROW + jj] = make_float2(lo, hi);
}

// ---------- pass 2: conv + segment mean; ci-plane pipelined, 4 CTAs/SM ----------
// Block (32,4). Thread (tx,ty): out rows 2ty,2ty+1; pair cols q=tx+32m (m=0..3)
// covering out columns {q, q+128}. Stripe = 8 rows.
__global__ void __launch_bounds__(128, 4) conv_kernel(
    const float* __restrict__ Wt,   // [E,3,3,4,4]
    const float* __restrict__ Bs,   // [E,3]
    const int*   __restrict__ esrc,
    const int*   __restrict__ edst,
    float*       __restrict__ out)  // [12,4,3,256,256]
{
  __shared__ __align__(16) float2 slot[2][PLANE_F2];     // 23.2 KB
  __shared__ __align__(16) float2 w_all[4*144];          // 4.6 KB
  __shared__ int s_eidx[4], s_src[4], s_deg;

  const int v   = blockIdx.z;
  const int b   = blockIdx.y;
  const int y0  = blockIdx.x * 8;
  const int tx  = threadIdx.x;
  const int ty  = threadIdx.y;
  const int tid = ty*32 + tx;
  const int r0  = 2*ty;

  const uint32_t slot_u32 = (uint32_t)__cvta_generic_to_shared(&slot[0][0]);

  if (tid == 0){
    int d = 0;
    for (int e=0; e<EE; e++)
      if (__ldg(&edst[e]) == v){ s_eidx[d]=e; s_src[d]=__ldg(&esrc[e]); d++; }
    s_deg = d;
  }
  __syncthreads();
  const int deg = s_deg;

  for (int i=0; i<deg; i++)
    for (int j=tid; j<144; j+=128){
      float w = __ldg(&Wt[s_eidx[i]*144 + j]);
      w_all[i*144 + j] = make_float2(w, w);
    }
  float bsum[3] = {0.f,0.f,0.f};
  for (int i=0; i<deg; i++)
    #pragma unroll
    for (int co=0; co<3; co++) bsum[co] += __ldg(&Bs[s_eidx[i]*3+co]);

  ull acc[3][2][4];
  #pragma unroll
  for (int co=0; co<3; co++)
    #pragma unroll
    for (int rl=0; rl<2; rl++)
      #pragma unroll
      for (int m=0; m<4; m++) acc[co][rl][m] = 0ull;

  // Fill one ci-plane (node,ci) into slot si. OOR rows -> STS zeros.
  auto fill = [&](int si, int node, int ci){
    const float2* gbase = g_pk + ((((size_t)node*BB + b)*CC + ci)*HH)*(size_t)PROW;
    uint32_t sb = slot_u32 + (uint32_t)(si*PLANE_BYTES);
    char* sgen = (char*)&slot[si][0];
    for (int t = tid; t < TROWS*66; t += 128){
      int rr = t / 66;                 // 0..10
      int c  = t - rr*66;              // 16B chunk
      int gy = y0 + rr - 1;
      uint32_t off = (uint32_t)(rr*(PROW*8) + c*16);
      if ((unsigned)gy < (unsigned)HH)
        cp16(sb + off, (const char*)(gbase + (size_t)gy*PROW) + c*16);
      else
        *(float4*)(sgen + off) = make_float4(0.f,0.f,0.f,0.f);
    }
  };

  const int S = 3*deg;
  fill(0, s_src[0], 0);
  asm volatile("cp.async.commit_group;" ::: "memory");

  for (int s=0; s<S; s++){
    asm volatile("cp.async.wait_group 0;" ::: "memory");
    __syncthreads();                       // publish plane s; slot (s+1)&1 free
    if (s+1 < S){
      int s1 = s+1, i1 = s1/3;
      fill(s1 & 1, s_src[i1], s1 - 3*i1);
      asm volatile("cp.async.commit_group;" ::: "memory");
    }
    const int i  = s/3;
    const int ci = s - 3*i;
    const ull* rows  = (const ull*)&slot[s & 1][0];
    const float2* wb = w_all + i*144;

    #pragma unroll
    for (int mh=0; mh<2; mh++){
      const int base0 = tx + 64*mh;        // m = 2mh, 2mh+1
      ull R0[8], R1[8];
      {
        const ull* rp = rows + r0*PROW;
        #pragma unroll
        for (int mm=0; mm<2; mm++)
          #pragma unroll
          for (int k=0; k<4; k++) R0[mm*4+k] = rp[base0 + 32*mm + k];
      }
      #pragma unroll
      for (int ky=0; ky<4; ky++){
        const ull* rq = rows + (r0+ky+1)*PROW;
        #pragma unroll
        for (int mm=0; mm<2; mm++)
          #pragma unroll
          for (int k=0; k<4; k++) R1[mm*4+k] = rq[base0 + 32*mm + k];

        #pragma unroll
        for (int co=0; co<3; co++){
          const ulonglong2* wp = (const ulonglong2*)(wb + (co*3+ci)*16 + ky*4);
          ulonglong2 w01 = wp[0], w23 = wp[1];   // broadcast LDS.128
          #pragma unroll
          for (int mm=0; mm<2; mm++){
            const int m = 2*mh + mm;
            acc[co][0][m] = ffma2(R0[mm*4+0], w01.x, acc[co][0][m]);
            acc[co][0][m] = ffma2(R0[mm*4+1], w01.y, acc[co][0][m]);
            acc[co][0][m] = ffma2(R0[mm*4+2], w23.x, acc[co][0][m]);
            acc[co][0][m] = ffma2(R0[mm*4+3], w23.y, acc[co][0][m]);
            acc[co][1][m] = ffma2(R1[mm*4+0], w01.x, acc[co][1][m]);
            acc[co][1][m] = ffma2(R1[mm*4+1], w01.y, acc[co][1][m]);
            acc[co][1][m] = ffma2(R1[mm*4+2], w23.x, acc[co][1][m]);
            acc[co][1][m] = ffma2(R1[mm*4+3], w23.y, acc[co][1][m]);
          }
        }
        #pragma unroll
        for (int j=0; j<8; j++) R0[j] = R1[j];   // renamed by full unroll
      }
    }
  }

  // Epilogue: bias + mean, store both columns of each pair.
  const float inv = 1.f / (float)deg;
  #pragma unroll
  for (int co=0; co<3; co++){
    #pragma unroll
    for (int rl=0; rl<2; rl++){
      float* ob = out + (((size_t)v*BB + b)*CC + co)*HWSZ + (y0 + r0 + rl)*WW;
      #pragma unroll
      for (int m=0; m<4; m++){
        float lo, hi;
        upk2(acc[co][rl][m], lo, hi);
        int x = tx + 32*m;
        ob[x]       = (lo + bsum[co]) * inv;
        ob[x + 128] = (hi + bsum[co]) * inv;
      }
    }
  }
}

extern "C" void kernel_launch(void* const* d_in, const int* in_sizes, int n_in,
                              void* d_out, int out_size){
  const float* states  = (const float*)d_in[0];
  const float* weights = (const float*)d_in[1];
  const float* bias    = (const float*)d_in[2];
  const int*   esrc    = (const int*)d_in[3];
  const int*   edst    = (const int*)d_in[4];
  float*       out     = (float*)d_out;

  const int npairs = NROWS_TOTAL * PROW;
  sigmoid_pack_kernel<<<(npairs + 255)/256, 256>>>(states, npairs);

  dim3 grid(HH/8, BB, N_REAL);
  dim3 block(32, 4);
  conv_kernel<<<grid, block>>>(weights, bias, esrc, edst, out);
}

// round 8
// speedup vs baseline: 1.1784x; 1.0088x over previous
#include <cuda_runtime.h>
#include <cstdint>

#define N_NODES 13
#define N_REAL  12
#define BB      4
#define CC      3
#define HH      256
#define WW      256
#define EE      37
#define HWSZ    (HH*WW)

// Packed activation row: 132 float2. idx 0 = {0, a[127]}, idx 1+j = {a[j], a[j+128]}
// (j=0..127), idx 129 = {a[128],0}, idx 130 = {a[129],0}, idx 131 = pad.
#define PROW 132
#define NROWS_TOTAL (N_NODES*BB*CC*HH)
#define TROWS 11
#define PLANE_F2 (TROWS*PROW)          // 1452 float2 per ci-plane tile
#define PLANE_BYTES (PLANE_F2*8)       // 11616 B
#define NSLOT 4
#define DYN_BYTES (NSLOT*PLANE_BYTES)  // 46464 B (dynamic smem)
typedef unsigned long long ull;

__device__ float2 g_pk[NROWS_TOTAL*PROW];    // packed sigmoid activations (~42 MB)
__device__ float2 g_wpk[EE*144];             // duplicated {w,w} weight pairs
__device__ int    g_deg[N_REAL];
__device__ int    g_esr[N_REAL][4];          // src node per incoming edge
__device__ int    g_eid[N_REAL][4];          // edge index per incoming edge
__device__ float  g_bsum[N_REAL][3];         // summed bias per dst

__device__ __forceinline__ void upk2(ull v, float& lo, float& hi){
  asm("mov.b64 {%0, %1}, %2;" : "=f"(lo), "=f"(hi) : "l"(v));
}
__device__ __forceinline__ ull ffma2(ull a, ull b, ull c){
  ull d; asm("fma.rn.f32x2 %0, %1, %2, %3;" : "=l"(d) : "l"(a), "l"(b), "l"(c));
  return d;
}
__device__ __forceinline__ void cp16(uint32_t s, const void* g){
  asm volatile("cp.async.cg.shared.global [%0], [%1], 16;" :: "r"(s), "l"(g));
}
__device__ __forceinline__ float sigf(float x){
  return __fdividef(1.f, 1.f + __expf(-x));
}

// ---------- setup: edge lists, weight dup, bias sums ----------
__global__ void setup_kernel(const float* __restrict__ Wt, const float* __restrict__ Bs,
                             const int* __restrict__ esrc, const int* __restrict__ edst){
  int t = blockIdx.x*blockDim.x + threadIdx.x;
  if (t < EE*144){ float w = __ldg(&Wt[t]); g_wpk[t] = make_float2(w, w); }
  if (t < N_REAL){
    int d = 0; float b0=0.f, b1=0.f, b2=0.f;
    for (int e=0; e<EE; e++)
      if (__ldg(&edst[e]) == t){
        g_esr[t][d] = __ldg(&esrc[e]);
        g_eid[t][d] = e;
        b0 += __ldg(&Bs[e*3+0]); b1 += __ldg(&Bs[e*3+1]); b2 += __ldg(&Bs[e*3+2]);
        d++;
      }
    g_deg[t] = d;
    g_bsum[t][0]=b0; g_bsum[t][1]=b1; g_bsum[t][2]=b2;
  }
}

// ---------- pass 1: sigmoid + pack (each element read once) ----------
__global__ void sigmoid_pack_main(const float* __restrict__ x, int n){
  int idx = blockIdx.x*blockDim.x + threadIdx.x;
  if (idx >= n) return;
  int rid = idx >> 5, q = idx & 31;
  const float4* in4 = (const float4*)(x + (size_t)rid*WW);
  float4 lo = __ldg(in4 + q);
  float4 hi = __ldg(in4 + q + 32);
  float2* o = g_pk + (size_t)rid*PROW + 1 + 4*q;
  o[0] = make_float2(sigf(lo.x), sigf(hi.x));
  o[1] = make_float2(sigf(lo.y), sigf(hi.y));
  o[2] = make_float2(sigf(lo.z), sigf(hi.z));
  o[3] = make_float2(sigf(lo.w), sigf(hi.w));
}
__global__ void sigmoid_pack_halo(const float* __restrict__ x, int nrows){
  int rid = blockIdx.x*blockDim.x + threadIdx.x;
  if (rid >= nrows) return;
  const float* in = x + (size_t)rid*WW;
  float s127 = sigf(__ldg(in+127)), s128 = sigf(__ldg(in+128)), s129 = sigf(__ldg(in+129));
  float2* row = g_pk + (size_t)rid*PROW;
  row[0]   = make_float2(0.f,  s127);
  row[129] = make_float2(s128, 0.f);
  row[130] = make_float2(s129, 0.f);
  row[131] = make_float2(0.f,  0.f);
}

// ---------- pass 2: conv + segment mean; depth-3 plane pipeline, 4 CTAs/SM ----------
extern __shared__ __align__(16) float2 dynslot[];   // NSLOT planes

__global__ void __launch_bounds__(128, 4) conv_kernel(float* __restrict__ out){
  __shared__ __align__(16) float2 w_all[4*144];     // 4.6 KB static

  const int v   = blockIdx.z;
  const int b   = blockIdx.y;
  const int y0  = blockIdx.x * 8;
  const int tx  = threadIdx.x;
  const int ty  = threadIdx.y;
  const int tid = ty*32 + tx;
  const int r0  = 2*ty;

  const uint32_t slot_u32 = (uint32_t)__cvta_generic_to_shared(&dynslot[0]);
  const uint32_t wall_u32 = (uint32_t)__cvta_generic_to_shared(&w_all[0]);

  const int deg = g_deg[v];
  int src[4], eid[4];
  #pragma unroll
  for (int i=0; i<4; i++){ src[i] = g_esr[v][i]; eid[i] = g_eid[v][i]; }

  ull acc[3][2][4];
  #pragma unroll
  for (int co=0; co<3; co++)
    #pragma unroll
    for (int rl=0; rl<2; rl++)
      #pragma unroll
      for (int m=0; m<4; m++) acc[co][rl][m] = 0ull;

  // Fill one ci-plane into slot si (cp.async; OOR rows zeroed via STS).
  auto fill = [&](int si, int node, int ci){
    const float2* gbase = g_pk + ((((size_t)node*BB + b)*CC + ci)*HH)*(size_t)PROW;
    uint32_t sb = slot_u32 + (uint32_t)(si*PLANE_BYTES);
    char* sgen = (char*)&dynslot[si*PLANE_F2];
    for (int t = tid; t < TROWS*66; t += 128){
      int rr = t / 66;
      int c  = t - rr*66;
      int gy = y0 + rr - 1;
      uint32_t off = (uint32_t)(rr*(PROW*8) + c*16);
      if ((unsigned)gy < (unsigned)HH)
        cp16(sb + off, (const char*)(gbase + (size_t)gy*PROW) + c*16);
      else
        *(float4*)(sgen + off) = make_float4(0.f,0.f,0.f,0.f);
    }
  };

  const int S = 3*deg;
  // Prologue group 0: weights + plane 0.
  for (int t = tid; t < deg*72; t += 128){
    int e = t / 72, c = t - e*72;
    cp16(wall_u32 + (uint32_t)((e*72 + c)*16),
         (const char*)(g_wpk + eid[e]*144) + c*16);
  }
  fill(0, src[0], 0);
  asm volatile("cp.async.commit_group;" ::: "memory");
  fill(1, src[0], 1);
  asm volatile("cp.async.commit_group;" ::: "memory");
  fill(2, src[0], 2);
  asm volatile("cp.async.commit_group;" ::: "memory");

  for (int s=0; s<S; s++){
    asm volatile("cp.async.wait_group 2;" ::: "memory");
    __syncthreads();                    // publish plane s; slot (s-1)%4 now free
    if (s+3 < S){
      int s3 = s+3, i3 = s3/3;
      fill(s3 & (NSLOT-1), src[i3], s3 - 3*i3);
    }
    asm volatile("cp.async.commit_group;" ::: "memory");   // empty group OK at tail

    const int i  = s/3;
    const int ci = s - 3*i;
    const ull* rows  = (const ull*)&dynslot[(s & (NSLOT-1))*PLANE_F2];
    const float2* wb = w_all + i*144;

    #pragma unroll
    for (int mh=0; mh<2; mh++){
      const int base0 = tx + 64*mh;
      ull R0[8], R1[8];
      {
        const ull* rp = rows + r0*PROW;
        #pragma unroll
        for (int mm=0; mm<2; mm++)
          #pragma unroll
          for (int k=0; k<4; k++) R0[mm*4+k] = rp[base0 + 32*mm + k];
      }
      #pragma unroll
      for (int ky=0; ky<4; ky++){
        const ull* rq = rows + (r0+ky+1)*PROW;
        #pragma unroll
        for (int mm=0; mm<2; mm++)
          #pragma unroll
          for (int k=0; k<4; k++) R1[mm*4+k] = rq[base0 + 32*mm + k];

        #pragma unroll
        for (int co=0; co<3; co++){
          const ulonglong2* wp = (const ulonglong2*)(wb + (co*3+ci)*16 + ky*4);
          ulonglong2 w01 = wp[0], w23 = wp[1];   // broadcast LDS.128
          #pragma unroll
          for (int mm=0; mm<2; mm++){
            const int m = 2*mh + mm;
            acc[co][0][m] = ffma2(R0[mm*4+0], w01.x, acc[co][0][m]);
            acc[co][0][m] = ffma2(R0[mm*4+1], w01.y, acc[co][0][m]);
            acc[co][0][m] = ffma2(R0[mm*4+2], w23.x, acc[co][0][m]);
            acc[co][0][m] = ffma2(R0[mm*4+3], w23.y, acc[co][0][m]);
            acc[co][1][m] = ffma2(R1[mm*4+0], w01.x, acc[co][1][m]);
            acc[co][1][m] = ffma2(R1[mm*4+1], w01.y, acc[co][1][m]);
            acc[co][1][m] = ffma2(R1[mm*4+2], w23.x, acc[co][1][m]);
            acc[co][1][m] = ffma2(R1[mm*4+3], w23.y, acc[co][1][m]);
          }
        }
        #pragma unroll
        for (int j=0; j<8; j++) R0[j] = R1[j];   // renamed by full unroll
      }
    }
  }

  const float inv = 1.f / (float)deg;
  float bsum[3] = { g_bsum[v][0], g_bsum[v][1], g_bsum[v][2] };
  #pragma unroll
  for (int co=0; co<3; co++){
    #pragma unroll
    for (int rl=0; rl<2; rl++){
      float* ob = out + (((size_t)v*BB + b)*CC + co)*HWSZ + (y0 + r0 + rl)*WW;
      #pragma unroll
      for (int m=0; m<4; m++){
        float lo, hi;
        upk2(acc[co][rl][m], lo, hi);
        int x = tx + 32*m;
        ob[x]       = (lo + bsum[co]) * inv;
        ob[x + 128] = (hi + bsum[co]) * inv;
      }
    }
  }
}

extern "C" void kernel_launch(void* const* d_in, const int* in_sizes, int n_in,
                              void* d_out, int out_size){
  const float* states  = (const float*)d_in[0];
  const float* weights = (const float*)d_in[1];
  const float* bias    = (const float*)d_in[2];
  const int*   esrc    = (const int*)d_in[3];
  const int*   edst    = (const int*)d_in[4];
  float*       out     = (float*)d_out;

  setup_kernel<<<(EE*144 + 255)/256, 256>>>(weights, bias, esrc, edst);

  const int nmain = NROWS_TOTAL * 32;          // 1,277,952 threads
  sigmoid_pack_main<<<(nmain + 255)/256, 256>>>(states, nmain);
  sigmoid_pack_halo<<<(NROWS_TOTAL + 255)/256, 256>>>(states, NROWS_TOTAL);

  static int smem_set = 0;
  if (!smem_set){
    cudaFuncSetAttribute(conv_kernel, cudaFuncAttributeMaxDynamicSharedMemorySize,
                         DYN_BYTES);
    smem_set = 1;
  }
  dim3 grid(HH/8, BB, N_REAL);
  dim3 block(32, 4);
  conv_kernel<<<grid, block, DYN_BYTES>>>(out);
}

// round 9
// speedup vs baseline: 1.2748x; 1.0818x over previous
#include <cuda_runtime.h>
#include <cstdint>

#define N_NODES 13
#define N_REAL  12
#define BB      4
#define CC      3
#define HH      256
#define WW      256
#define EE      37
#define HWSZ    (HH*WW)

// Packed activation row: 132 float2. idx 0 = {0, a[127]}, idx 1+j = {a[j], a[j+128]}
// (j=0..127), idx 129 = {a[128],0}, idx 130 = {a[129],0}, idx 131 = pad.
#define PROW 132
#define NROWS_TOTAL (N_NODES*BB*CC*HH)
#define TROWS 11
#define PLANE_F2 (TROWS*PROW)          // 1452 float2 per ci-plane tile
#define PLANE_BYTES (PLANE_F2*8)       // 11616 B
#define NSLOT 4
#define DYN_BYTES (NSLOT*PLANE_BYTES)  // 46464 B dynamic smem
#define NTILES 1536                    // 12 v * 4 b * 32 stripes
#define NCTA 592                       // 4 CTAs/SM * 148 SMs
typedef unsigned long long ull;

__device__ float2 g_pk[NROWS_TOTAL*PROW];    // packed sigmoid activations (~42 MB)
__device__ float2 g_wpk[EE*144];             // duplicated {w,w} weight pairs
__device__ int    g_deg[N_REAL];
__device__ int    g_esr[N_REAL][4];
__device__ int    g_eid[N_REAL][4];
__device__ float  g_bsum[N_REAL][3];
__device__ unsigned g_ctr;                   // tile work-steal counter

__device__ __forceinline__ void upk2(ull v, float& lo, float& hi){
  asm("mov.b64 {%0, %1}, %2;" : "=f"(lo), "=f"(hi) : "l"(v));
}
__device__ __forceinline__ ull ffma2(ull a, ull b, ull c){
  ull d; asm("fma.rn.f32x2 %0, %1, %2, %3;" : "=l"(d) : "l"(a), "l"(b), "l"(c));
  return d;
}
__device__ __forceinline__ void cp16(uint32_t s, const void* g){
  asm volatile("cp.async.cg.shared.global [%0], [%1], 16;" :: "r"(s), "l"(g));
}
__device__ __forceinline__ float sigf(float x){
  return __fdividef(1.f, 1.f + __expf(-x));
}

// ---------- pass 1: setup (block 0) + sigmoid pack + halo (blocks 1..) ----------
__global__ void sigmoid_pack_all(const float* __restrict__ x,
                                 const float* __restrict__ Wt,
                                 const float* __restrict__ Bs,
                                 const int*   __restrict__ esrc,
                                 const int*   __restrict__ edst){
  if (blockIdx.x == 0){
    int t = threadIdx.x;
    for (int i=t; i<EE*144; i+=256){ float w=__ldg(&Wt[i]); g_wpk[i]=make_float2(w,w); }
    if (t < N_REAL){
      int d=0; float b0=0.f,b1=0.f,b2=0.f;
      for (int e=0; e<EE; e++)
        if (__ldg(&edst[e]) == t){
          g_esr[t][d]=__ldg(&esrc[e]); g_eid[t][d]=e;
          b0+=__ldg(&Bs[e*3+0]); b1+=__ldg(&Bs[e*3+1]); b2+=__ldg(&Bs[e*3+2]);
          d++;
        }
      g_deg[t]=d; g_bsum[t][0]=b0; g_bsum[t][1]=b1; g_bsum[t][2]=b2;
    }
    if (t == 0) g_ctr = 0u;
    return;
  }
  int idx = (blockIdx.x-1)*256 + threadIdx.x;     // 0 .. NROWS_TOTAL*32-1
  int rid = idx >> 5, q = idx & 31;
  const float4* in4 = (const float4*)(x + (size_t)rid*WW);
  float4 lo = __ldg(in4 + q);
  float4 hi = __ldg(in4 + q + 32);
  float slx=sigf(lo.x), sly=sigf(lo.y), slz=sigf(lo.z), slw=sigf(lo.w);
  float shx=sigf(hi.x), shy=sigf(hi.y), shz=sigf(hi.z), shw=sigf(hi.w);
  float2* row = g_pk + (size_t)rid*PROW;
  float2* o = row + 1 + 4*q;
  o[0] = make_float2(slx, shx);
  o[1] = make_float2(sly, shy);
  o[2] = make_float2(slz, shz);
  o[3] = make_float2(slw, shw);
  if (q == 31) row[0]   = make_float2(0.f, slw);    // {0, s(a127)}
  if (q == 0){
    row[129] = make_float2(shx, 0.f);               // {s(a128), 0}
    row[130] = make_float2(shy, 0.f);               // {s(a129), 0}
    row[131] = make_float2(0.f, 0.f);
  }
}

// ---------- conv compute helpers ----------
__device__ __forceinline__ void load8(ull (&R)[8], const ull* rows, int rowidx, int base0){
  const ull* rp = rows + rowidx*PROW;
  #pragma unroll
  for (int mm=0; mm<2; mm++)
    #pragma unroll
    for (int k=0; k<4; k++) R[mm*4+k] = rp[base0 + 32*mm + k];
}
// T = input rows for out row rl=0, Bt = rows for rl=1 (this ky).
__device__ __forceinline__ void fma_ky(ull (&acc)[3][2][4],
                                       const ull (&T)[8], const ull (&Bt)[8],
                                       const float2* wb, int ci, int ky, int mh){
  #pragma unroll
  for (int co=0; co<3; co++){
    const ulonglong2* wp = (const ulonglong2*)(wb + (co*3+ci)*16 + ky*4);
    ulonglong2 w01 = wp[0], w23 = wp[1];    // broadcast LDS.128
    #pragma unroll
    for (int mm=0; mm<2; mm++){
      const int m = 2*mh + mm;
      acc[co][0][m] = ffma2(T[mm*4+0],  w01.x, acc[co][0][m]);
      acc[co][0][m] = ffma2(T[mm*4+1],  w01.y, acc[co][0][m]);
      acc[co][0][m] = ffma2(T[mm*4+2],  w23.x, acc[co][0][m]);
      acc[co][0][m] = ffma2(T[mm*4+3],  w23.y, acc[co][0][m]);
      acc[co][1][m] = ffma2(Bt[mm*4+0], w01.x, acc[co][1][m]);
      acc[co][1][m] = ffma2(Bt[mm*4+1], w01.y, acc[co][1][m]);
      acc[co][1][m] = ffma2(Bt[mm*4+2], w23.x, acc[co][1][m]);
      acc[co][1][m] = ffma2(Bt[mm*4+3], w23.y, acc[co][1][m]);
    }
  }
}

// ---------- pass 2: persistent conv + segment mean ----------
extern __shared__ __align__(16) float2 dynslot[];

__global__ void __launch_bounds__(128, 4) conv_kernel(float* __restrict__ out){
  __shared__ __align__(16) float2 w_all[4*144];
  __shared__ unsigned s_tile;

  const int tx  = threadIdx.x;
  const int ty  = threadIdx.y;
  const int tid = ty*32 + tx;
  const int r0  = 2*ty;

  const uint32_t slot_u32 = (uint32_t)__cvta_generic_to_shared(&dynslot[0]);
  const uint32_t wall_u32 = (uint32_t)__cvta_generic_to_shared(&w_all[0]);

  int prev_v = -1, deg = 0;
  int src[4] = {0,0,0,0}, eid[4] = {0,0,0,0};
  float bsum[3] = {0.f,0.f,0.f};

  for (;;){
    if (tid == 0) s_tile = atomicAdd(&g_ctr, 1u);
    __syncthreads();                       // tile start: also fences slot/w_all reuse
    const unsigned t = s_tile;
    if (t >= NTILES) break;
    const int v   = (int)(t >> 7);
    const int rem = (int)(t & 127u);
    const int b   = rem >> 5;
    const int y0  = (rem & 31) * 8;
    const bool vch = (v != prev_v);
    if (vch){
      prev_v = v;
      deg = g_deg[v];
      #pragma unroll
      for (int i=0; i<4; i++){ src[i] = g_esr[v][i]; eid[i] = g_eid[v][i]; }
      bsum[0]=g_bsum[v][0]; bsum[1]=g_bsum[v][1]; bsum[2]=g_bsum[v][2];
    }

    // Fill one ci-plane into slot si.
    auto fill = [&](int si, int node, int ci){
      const float2* gplane = g_pk + ((((size_t)node*BB + b)*CC + ci)*HH)*(size_t)PROW;
      uint32_t sb = slot_u32 + (uint32_t)(si*PLANE_BYTES);
      for (int w = tid; w < TROWS*66; w += 128){
        int rr = w / 66;
        int c  = w - rr*66;
        int gy = y0 + rr - 1;
        uint32_t off = (uint32_t)(rr*(PROW*8) + c*16);
        if ((unsigned)gy < (unsigned)HH)
          cp16(sb + off, (const char*)(gplane + (size_t)gy*PROW) + c*16);
        else
          asm volatile("st.shared.v4.b32 [%0], {%1,%1,%1,%1};"
                       :: "r"(sb + off), "r"(0) : "memory");
      }
    };

    // Prologue: (weights if v changed) + planes 0..2 as 3 groups.
    if (vch){
      for (int q = tid; q < deg*72; q += 128){
        int e = q/72, c = q - e*72;
        cp16(wall_u32 + (uint32_t)((e*72 + c)*16),
             (const char*)(g_wpk + eid[e]*144) + c*16);
      }
    }
    fill(0, src[0], 0);
    asm volatile("cp.async.commit_group;" ::: "memory");
    fill(1, src[0], 1);
    asm volatile("cp.async.commit_group;" ::: "memory");
    fill(2, src[0], 2);
    asm volatile("cp.async.commit_group;" ::: "memory");

    ull acc[3][2][4];
    #pragma unroll
    for (int co=0; co<3; co++)
      #pragma unroll
      for (int rl=0; rl<2; rl++)
        #pragma unroll
        for (int m=0; m<4; m++) acc[co][rl][m] = 0ull;

    const int S = 3*deg;
    for (int s=0; s<S; s++){
      asm volatile("cp.async.wait_group 2;" ::: "memory");
      __syncthreads();                  // publish plane s
      if (s+3 < S){
        int s3 = s+3, i3 = s3/3;
        fill(s3 & (NSLOT-1), src[i3], s3 - 3*i3);
      }
      asm volatile("cp.async.commit_group;" ::: "memory");

      const int i  = s/3;
      const int ci = s - 3*i;
      const ull* rows  = (const ull*)&dynslot[(s & (NSLOT-1))*PLANE_F2];
      const float2* wb = w_all + i*144;

      #pragma unroll
      for (int mh=0; mh<2; mh++){
        const int base0 = tx + 64*mh;
        ull Ra[8], Rb[8];
        load8(Ra, rows, r0,   base0);
        load8(Rb, rows, r0+1, base0); fma_ky(acc, Ra, Rb, wb, ci, 0, mh);
        load8(Ra, rows, r0+2, base0); fma_ky(acc, Rb, Ra, wb, ci, 1, mh);
        load8(Rb, rows, r0+3, base0); fma_ky(acc, Ra, Rb, wb, ci, 2, mh);
        load8(Ra, rows, r0+4, base0); fma_ky(acc, Rb, Ra, wb, ci, 3, mh);
      }
    }

    // Epilogue: bias + mean, store both columns of each pair.
    const float inv = 1.f / (float)deg;
    #pragma unroll
    for (int co=0; co<3; co++){
      #pragma unroll
      for (int rl=0; rl<2; rl++){
        float* ob = out + (((size_t)v*BB + b)*CC + co)*HWSZ + (y0 + r0 + rl)*WW;
        #pragma unroll
        for (int m=0; m<4; m++){
          float lo, hi;
          upk2(acc[co][rl][m], lo, hi);
          int x = tx + 32*m;
          ob[x]       = (lo + bsum[co]) * inv;
          ob[x + 128] = (hi + bsum[co]) * inv;
        }
      }
    }
  }
}

extern "C" void kernel_launch(void* const* d_in, const int* in_sizes, int n_in,
                              void* d_out, int out_size){
  const float* states  = (const float*)d_in[0];
  const float* weights = (const float*)d_in[1];
  const float* bias    = (const float*)d_in[2];
  const int*   esrc    = (const int*)d_in[3];
  const int*   edst    = (const int*)d_in[4];
  float*       out     = (float*)d_out;

  const int nmain_blocks = (NROWS_TOTAL*32)/256;     // 4992
  sigmoid_pack_all<<<nmain_blocks + 1, 256>>>(states, weights, bias, esrc, edst);

  static int smem_set = 0;
  if (!smem_set){
    cudaFuncSetAttribute(conv_kernel, cudaFuncAttributeMaxDynamicSharedMemorySize,
                         DYN_BYTES);
    smem_set = 1;
  }
  conv_kernel<<<NCTA, dim3(32,4), DYN_BYTES>>>(out);
}